// round 3
// baseline (speedup 1.0000x reference)
#include <cuda_runtime.h>
#include <cstdint>

// Fixed problem shapes
constexpr int B_ = 32, N_ = 128, K_ = 16, F_ = 256, D_ = 256;
constexpr int ATOMS = 8;                 // atoms per CTA
constexpr int ROWS = ATOMS * K_;         // 128 neighbor GEMM rows
constexpr int THREADS = 512;             // 16 warps
constexpr int TF = 16;                   // F per stage
constexpr int NST = F_ / TF;             // 16 stages

constexpr int PADA = 264;                // nb / C row stride (floats), 264 % 32 == 8
constexpr int WPS  = 520;                // W-tile plane stride (floats), 520 % 32 == 8

// shared layout (floats)
constexpr int OFF_NB  = 0;                        // 136 rows x 264 (nb tf32 + x rows 128..135; later C)
constexpr int OFF_WN  = OFF_NB + 136 * PADA;      // 8 planes x 520
constexpr int OFF_WAT = OFF_WN + 8 * WPS;         // 8 planes x 520
constexpr int OFF_AFS = OFF_WAT + 8 * WPS;        // 8 x 264 af output
constexpr int OFF_SM  = OFF_AFS + 8 * PADA;       // 128
constexpr int OFF_AM  = OFF_SM + ROWS;            // 128
constexpr int OFF_RED = OFF_AM + ROWS;            // 2 halves x 8 warps x 16
constexpr int OFF_LN  = OFF_RED + 256;            // 2 halves x 16
constexpr int SMEM_FL = OFF_LN + 32;              // ~46880 floats = 187,520 B

__device__ __forceinline__ float to_tf32(float x) {
    float y;
    asm("cvt.rna.tf32.f32 %0, %1;" : "=f"(y) : "f"(x));
    return y;
}

__device__ __forceinline__ void mma_tf32(float c[4], uint32_t a0, uint32_t a1,
                                         uint32_t a2, uint32_t a3,
                                         uint32_t b0, uint32_t b1) {
    asm volatile(
        "mma.sync.aligned.m16n8k8.row.col.f32.tf32.tf32.f32 "
        "{%0,%1,%2,%3},{%4,%5,%6,%7},{%8,%9},{%0,%1,%2,%3};"
        : "+f"(c[0]), "+f"(c[1]), "+f"(c[2]), "+f"(c[3])
        : "r"(a0), "r"(a1), "r"(a2), "r"(a3), "r"(b0), "r"(b1));
}

__global__ void __launch_bounds__(THREADS, 1)
gnn_atom_aggregate_kernel(const float* __restrict__ atom_feat,
                          const float* __restrict__ nbr_feat,
                          const float* __restrict__ smask,
                          const float* __restrict__ amask,
                          const float* __restrict__ Wa,
                          const float* __restrict__ ba,
                          const float* __restrict__ Wn,
                          const float* __restrict__ bn,
                          const float* __restrict__ wal,
                          const float* __restrict__ bal,
                          const float* __restrict__ gam,
                          const float* __restrict__ bet,
                          float* __restrict__ out)
{
    extern __shared__ float s[];
    const int tid  = threadIdx.x;
    const int blk  = blockIdx.x;
    const int lane = tid & 31;
    const int w    = tid >> 5;
    const int l4   = lane & 3;
    const int lr   = lane >> 2;

    // ---- prologue: pack nb (tf32, (f,f+4)-pair layout) + x rows + masks ----
    {
        const float4* nb_src = (const float4*)(nbr_feat + (size_t)blk * ROWS * F_);
#pragma unroll
        for (int i = 0; i < 16; i++) {
            int ft  = tid + i * THREADS;        // float4 id
            int row = ft >> 6;
            int c4  = ft & 63;
            float4 v = nb_src[ft];
            float* base = s + OFF_NB + row * PADA + (c4 >> 1) * 8 + (c4 & 1);
            base[0] = to_tf32(v.x); base[2] = to_tf32(v.y);
            base[4] = to_tf32(v.z); base[6] = to_tf32(v.w);
        }
        // atom features as rows 128..135 (same packed layout)
        {
            float4 v = ((const float4*)(atom_feat + (size_t)blk * ATOMS * F_))[tid];
            int row = 128 + (tid >> 6);
            int c4  = tid & 63;
            float* base = s + OFF_NB + row * PADA + (c4 >> 1) * 8 + (c4 & 1);
            base[0] = to_tf32(v.x); base[2] = to_tf32(v.y);
            base[4] = to_tf32(v.z); base[6] = to_tf32(v.w);
        }
        if (tid < 32)
            ((float4*)(s + OFF_SM))[tid] = ((const float4*)(smask + blk * ROWS))[tid];
        else if (tid < 64)
            ((float4*)(s + OFF_AM))[tid - 32] = ((const float4*)(amask + blk * ROWS))[tid - 32];
    }

    // W streaming: thread covers d = tid>>1, kk = tid&1 (8 f's per stage)
    const int gd = tid >> 1;
    const int gk = tid & 1;
    float4 cn0, cn1, ca0, ca1;    // current-stage W rows (8 floats each of Wn, Wa)
    {
        const float* pn = Wn + (size_t)gd * F_ + gk * 8;
        const float* pa = Wa + (size_t)gd * F_ + gk * 8;
        cn0 = *(const float4*)pn;  cn1 = *(const float4*)(pn + 4);
        ca0 = *(const float4*)pa;  ca1 = *(const float4*)(pa + 4);
    }

    float acc[2][8][4];
#pragma unroll
    for (int rf = 0; rf < 2; rf++)
#pragma unroll
        for (int j = 0; j < 8; j++)
#pragma unroll
            for (int q = 0; q < 4; q++) acc[rf][j][q] = 0.f;
    float afc[2][4];
#pragma unroll
    for (int u = 0; u < 2; u++)
#pragma unroll
        for (int q = 0; q < 4; q++) afc[u][q] = 0.f;

    const int rb = w >> 2;     // row block (32 rows)
    const int cb = w & 3;      // col block (64 cols)

    // ---- main loop ----
    for (int st = 0; st < NST; st++) {
        __syncthreads();   // previous-stage tile reads complete
        // store W tiles in packed plane layout; kk-rotated order -> conflict-free
        {
            const float* vn = (const float*)&cn0;   // cn0,cn1 contiguous? ensure via array
            float vnr[8] = {cn0.x, cn0.y, cn0.z, cn0.w, cn1.x, cn1.y, cn1.z, cn1.w};
            float var_[8] = {ca0.x, ca0.y, ca0.z, ca0.w, ca1.x, ca1.y, ca1.z, ca1.w};
            (void)vn;
#pragma unroll
            for (int i = 0; i < 4; i++) {
                int p = (i + 2 * gk) & 3;
                *(float2*)(s + OFF_WN + (gk * 4 + p) * WPS + gd * 2)
                    = make_float2(to_tf32(vnr[p]), to_tf32(vnr[p + 4]));
                *(float2*)(s + OFF_WAT + (gk * 4 + p) * WPS + gd * 2)
                    = make_float2(to_tf32(var_[p]), to_tf32(var_[p + 4]));
            }
        }
        __syncthreads();
        // prefetch next stage W rows (overlaps with MMA below)
        if (st + 1 < NST) {
            const float* pn = Wn + (size_t)gd * F_ + (st + 1) * TF + gk * 8;
            const float* pa = Wa + (size_t)gd * F_ + (st + 1) * TF + gk * 8;
            cn0 = *(const float4*)pn;  cn1 = *(const float4*)(pn + 4);
            ca0 = *(const float4*)pa;  ca1 = *(const float4*)(pa + 4);
        }

#pragma unroll
        for (int kk = 0; kk < 2; kk++) {
            const int g = st * 2 + kk;
            const float* nbb = s + OFF_NB + g * 8 + l4 * 2;
            // A fragments (row-pair packed)
            float2 a02_0 = *(const float2*)(nbb + (rb * 32 + lr) * PADA);
            float2 a13_0 = *(const float2*)(nbb + (rb * 32 + 8 + lr) * PADA);
            float2 a02_1 = *(const float2*)(nbb + (rb * 32 + 16 + lr) * PADA);
            float2 a13_1 = *(const float2*)(nbb + (rb * 32 + 24 + lr) * PADA);
            float2 afa   = *(const float2*)(nbb + (128 + lr) * PADA);
            const float* wnp = s + OFF_WN  + (kk * 4 + l4) * WPS + lr * 2;
            const float* wap = s + OFF_WAT + (kk * 4 + l4) * WPS + lr * 2;
#pragma unroll
            for (int j = 0; j < 8; j++) {
                float2 b = *(const float2*)(wnp + (cb * 64 + j * 8) * 2);
                mma_tf32(acc[0][j],
                         __float_as_uint(a02_0.x), __float_as_uint(a13_0.x),
                         __float_as_uint(a02_0.y), __float_as_uint(a13_0.y),
                         __float_as_uint(b.x), __float_as_uint(b.y));
                mma_tf32(acc[1][j],
                         __float_as_uint(a02_1.x), __float_as_uint(a13_1.x),
                         __float_as_uint(a02_1.y), __float_as_uint(a13_1.y),
                         __float_as_uint(b.x), __float_as_uint(b.y));
            }
            // af GEMM: this warp's two n8 fragments (jf = w*2+u), rows 8..15 zero
#pragma unroll
            for (int u = 0; u < 2; u++) {
                float2 b = *(const float2*)(wap + ((w * 2 + u) * 8) * 2);
                mma_tf32(afc[u],
                         __float_as_uint(afa.x), 0u,
                         __float_as_uint(afa.y), 0u,
                         __float_as_uint(b.x), __float_as_uint(b.y));
            }
        }
    }

    __syncthreads();   // all MMA reads of nb done before overwriting with C

    // ---- write C (nf, pre-bias) and af to smem ----
    {
        float* nf = s + OFF_NB;
#pragma unroll
        for (int rf = 0; rf < 2; rf++) {
            int r0 = rb * 32 + rf * 16 + lr;
#pragma unroll
            for (int j = 0; j < 8; j++) {
                int col = cb * 64 + j * 8 + 2 * l4;
                *(float2*)(nf + r0 * PADA + col)       = make_float2(acc[rf][j][0], acc[rf][j][1]);
                *(float2*)(nf + (r0 + 8) * PADA + col) = make_float2(acc[rf][j][2], acc[rf][j][3]);
            }
        }
#pragma unroll
        for (int u = 0; u < 2; u++) {
            int col = (w * 2 + u) * 8 + 2 * l4;
            *(float2*)(s + OFF_AFS + lr * PADA + col) = make_float2(afc[u][0], afc[u][1]);
        }
    }
    __syncthreads();

    // ---- epilogue: score -> softmax -> ctx -> LayerNorm ----
    const int dd = tid & 255;          // output feature
    const int ah = tid >> 8;           // atom half
    const float ba_d  = ba[dd];
    const float bn_d  = bn[dd];
    const float wal_d = wal[dd & 63];
    const float bal_s = bal[0];
    const float g_d   = gam[dd];
    const float be_d  = bet[dd];
    const int   wih   = (tid & 255) >> 5;  // warp-in-half
    const int   h     = dd >> 6;           // head
    float* s_red = s + OFF_RED + ah * 128;
    float* s_ln  = s + OFF_LN + ah * 16;
    const float* s_sm = s + OFF_SM;
    const float* s_am = s + OFF_AM;
    const float* nf   = s + OFF_NB;

#pragma unroll
    for (int ag = 0; ag < 4; ag++) {
        const int atom = ah * 4 + ag;
        const float afv = s[OFF_AFS + atom * PADA + dd] + ba_d;
        float nfr[K_], pp[K_];
#pragma unroll
        for (int k = 0; k < K_; k++) {
            nfr[k] = nf[(atom * 16 + k) * PADA + dd] + bn_d;
            float t = afv + nfr[k];
            t = (t > 0.f) ? t : 0.2f * t;      // leaky relu
            pp[k] = t * wal_d;
        }
#pragma unroll
        for (int off = 16; off; off >>= 1) {
#pragma unroll
            for (int k = 0; k < K_; k++)
                pp[k] += __shfl_xor_sync(0xffffffffu, pp[k], off);
        }
        if (lane == 0) {
#pragma unroll
            for (int k = 0; k < K_; k++) s_red[wih * 16 + k] = pp[k];
        }
        __syncthreads();

        float sc[K_];
        float mx = -3.4e38f;
#pragma unroll
        for (int k = 0; k < K_; k++) {
            sc[k] = s_red[(2 * h) * 16 + k] + s_red[(2 * h + 1) * 16 + k]
                  + bal_s + s_sm[atom * 16 + k];
            mx = fmaxf(mx, sc[k]);
        }
        float ssum = 0.f;
#pragma unroll
        for (int k = 0; k < K_; k++) { sc[k] = __expf(sc[k] - mx); ssum += sc[k]; }
        float inv = 1.f / ssum;
        float ctx = 0.f;
#pragma unroll
        for (int k = 0; k < K_; k++)
            ctx = fmaf(sc[k] * inv * s_am[atom * 16 + k], nfr[k], ctx);

        float s1 = ctx, s2 = ctx * ctx;
#pragma unroll
        for (int off = 16; off; off >>= 1) {
            s1 += __shfl_xor_sync(0xffffffffu, s1, off);
            s2 += __shfl_xor_sync(0xffffffffu, s2, off);
        }
        if (lane == 0) { s_ln[wih] = s1; s_ln[8 + wih] = s2; }
        __syncthreads();
        float S1 = 0.f, S2 = 0.f;
#pragma unroll
        for (int q = 0; q < 8; q++) { S1 += s_ln[q]; S2 += s_ln[8 + q]; }
        float mu  = S1 * (1.f / 256.f);
        float var = S2 * (1.f / 256.f) - mu * mu;
        float o = (ctx - mu) * rsqrtf(var + 1e-5f) * g_d + be_d;
        out[(size_t)(blk * ATOMS + atom) * D_ + dd] = o;
        __syncthreads();
    }
}

extern "C" void kernel_launch(void* const* d_in, const int* in_sizes, int n_in,
                              void* d_out, int out_size)
{
    const float* atom_feat = (const float*)d_in[0];
    const float* nbr_feat  = (const float*)d_in[1];
    const float* smask     = (const float*)d_in[2];
    const float* amask     = (const float*)d_in[3];
    const float* Wa        = (const float*)d_in[4];
    const float* ba        = (const float*)d_in[5];
    const float* Wn        = (const float*)d_in[6];
    const float* bn        = (const float*)d_in[7];
    const float* wal       = (const float*)d_in[8];
    const float* bal       = (const float*)d_in[9];
    const float* gam       = (const float*)d_in[10];
    const float* bet       = (const float*)d_in[11];
    float* out = (float*)d_out;

    cudaFuncSetAttribute(gnn_atom_aggregate_kernel,
                         cudaFuncAttributeMaxDynamicSharedMemorySize,
                         SMEM_FL * (int)sizeof(float));

    gnn_atom_aggregate_kernel<<<(B_ * N_) / ATOMS, THREADS,
                                SMEM_FL * sizeof(float)>>>(
        atom_feat, nbr_feat, smask, amask, Wa, ba, Wn, bn, wal, bal, gam, bet, out);
}